// round 3
// baseline (speedup 1.0000x reference)
#include <cuda_runtime.h>
#include <cuda_bf16.h>

// Problem constants: T=64, B=512, H=512.
#define T_DIM 64
#define B_DIM 512
#define H_DIM 512
#define H4    (H_DIM / 4)          // 128 float4 per row

// One block per batch lane b.
// Phase 1: replay ops (thread 0, stack in shared) -> s_src[t] (source time, -1=init)
// Phase 2: counting-sort t by source (parallel atomics + tiny serial prefix)
// Phase 3: streaming copy, one input-row load per DISTINCT source (register reuse)
__global__ void __launch_bounds__(512) fused_kernel(
    const float4* __restrict__ inputs,   // (T,B,H) as float4
    const float4* __restrict__ init_h,   // (H,)    as float4
    const int*    __restrict__ ops,      // (T,B)
    float4*       __restrict__ out)      // (T,B,H) as float4
{
    __shared__ int s_ops[T_DIM];
    __shared__ int s_stack[T_DIM + 2];
    __shared__ int s_src[T_DIM];          // source time per t; -1 => init_h
    __shared__ int s_cnt[T_DIM + 1];      // buckets for src+1 in [0,64]
    __shared__ int s_ord_t[T_DIM];        // t values grouped by source
    __shared__ int s_ord_s[T_DIM];        // matching source values

    const int b   = blockIdx.x;
    const int tid = threadIdx.x;

    if (tid < T_DIM) s_ops[tid] = ops[tid * B_DIM + b];
    if (tid < T_DIM + 1) s_cnt[tid] = 0;
    __syncthreads();

    // ---- Phase 1: serial stack replay (index bookkeeping only) ----
    if (tid == 0) {
        int pos = 0;
        int cur = -1;
        s_stack[0] = -1;
        #pragma unroll
        for (int t = 0; t < T_DIM; ++t) {
            int op = s_ops[t];
            s_stack[pos + 1] = t;                    // write x_t at pos+1
            pos += op;
            if (op == 1)       cur = t;
            else if (op == -1) cur = s_stack[pos];
            s_src[t] = cur;
        }
    }
    __syncthreads();

    // ---- Phase 2: counting sort of t by source ----
    if (tid < T_DIM) atomicAdd(&s_cnt[s_src[tid] + 1], 1);
    __syncthreads();
    if (tid == 0) {                                  // exclusive prefix (65 elems)
        int acc = 0;
        #pragma unroll
        for (int i = 0; i < T_DIM + 1; ++i) {
            int c = s_cnt[i]; s_cnt[i] = acc; acc += c;
        }
    }
    __syncthreads();
    if (tid < T_DIM) {
        int s = s_src[tid];
        int k = atomicAdd(&s_cnt[s + 1], 1);
        s_ord_t[k] = tid;
        s_ord_s[k] = s;
    }
    __syncthreads();

    // ---- Phase 3: grouped streaming copy ----
    // thread owns h4 = tid&127; group g = tid>>7 handles entries [16g, 16g+16).
    // Equal-source entries are contiguous -> load each distinct row ONCE.
    const int h4 = tid & (H4 - 1);
    const int g  = tid >> 7;
    const float4 vinit = init_h[h4];

    float4 v = vinit;
    int prev = -1;                                   // v currently holds init row
    #pragma unroll 4
    for (int i = 0; i < 16; ++i) {
        int e = (g << 4) + i;
        int t = s_ord_t[e];
        int s = s_ord_s[e];
        if (s != prev) {
            v = (s < 0) ? vinit
                        : inputs[((unsigned)(s * B_DIM + b)) * H4 + h4];
            prev = s;
        }
        // evict-first store: keep inputs resident in L2 across graph replays
        __stcs(&out[((unsigned)(t * B_DIM + b)) * H4 + h4], v);
    }
}

extern "C" void kernel_launch(void* const* d_in, const int* in_sizes, int n_in,
                              void* d_out, int out_size) {
    const float* inputs = (const float*)d_in[0];   // (T,B,H) f32
    const float* init_h = (const float*)d_in[1];   // (H,)    f32
    const int*   ops    = (const int*)d_in[2];     // (T,B)   i32
    float* out = (float*)d_out;                    // (T,B,H) f32

    fused_kernel<<<B_DIM, 512>>>(
        (const float4*)inputs, (const float4*)init_h, ops, (float4*)out);
}

// round 5
// speedup vs baseline: 1.1172x; 1.1172x over previous
#include <cuda_runtime.h>
#include <cuda_bf16.h>

// Problem constants: T=64, B=512, H=512.
#define T_DIM 64
#define B_DIM 512
#define H_DIM 512
#define H4    (H_DIM / 4)          // 128 float4 per row

// Grid: 1024 blocks x 256 threads. Block (b, half) covers lane b, 64 of the
// 128 float4 columns. Phase 1 is fully parallel:
//   P[t] = prefix_sum(ops)[t]  (P[-1] = 0)
//   src[t] = -1                      if P[t] == 0   (only initial lives at level 0)
//          = max{ u <= t : P[u-1] == P[t]-1 }  otherwise
// (every step u writes x_u at level P[u-1]+1; a read at level L sees the last
//  writer of L, which is exactly the max such u.)
__global__ void __launch_bounds__(256) fused_kernel(
    const float4* __restrict__ inputs,   // (T,B,H) as float4
    const float4* __restrict__ init_h,   // (H,)    as float4
    const int*    __restrict__ ops,      // (T,B)
    float4*       __restrict__ out)      // (T,B,H) as float4
{
    __shared__ int s_P[T_DIM + 1];       // s_P[u] = P[u-1], s_P[0] = 0
    __shared__ int s_src[T_DIM];
    __shared__ int s_w0;

    const int bid  = blockIdx.x;
    const int b    = bid >> 1;
    const int half = bid & 1;
    const int tid  = threadIdx.x;

    // ---- Phase 1a: two-warp inclusive scan of ops column b ----
    int p = 0;
    if (tid < T_DIM) {
        p = ops[tid * B_DIM + b];
        #pragma unroll
        for (int d = 1; d < 32; d <<= 1) {
            int n = __shfl_up_sync(0xFFFFFFFFu, p, d);
            if ((tid & 31) >= d) p += n;
        }
        if (tid == 31) s_w0 = p;
        if (tid == 0)  s_P[0] = 0;
    }
    __syncthreads();
    if (tid >= 32 && tid < T_DIM) p += s_w0;
    if (tid < T_DIM) s_P[tid + 1] = p;
    __syncthreads();

    // ---- Phase 1b: per-t backward search for the matching writer ----
    if (tid < T_DIM) {
        int Pt  = s_P[tid + 1];
        int src = -1;
        if (Pt > 0) {
            int target = Pt - 1;
            #pragma unroll 1
            for (int u = tid; u >= 0; --u) {
                if (s_P[u] == target) { src = u; break; }
            }
        }
        s_src[tid] = src;
    }
    __syncthreads();

    // ---- Phase 2: streaming gather-copy (64 t x 64 h4 per block) ----
    const int h4 = (half << 6) + (tid & 63);
    const int t0 = tid >> 6;                     // 0..3
    const float4 vinit = init_h[h4];

    #pragma unroll 4
    for (int i = 0; i < 16; ++i) {
        int t = t0 + (i << 2);
        int s = s_src[t];
        float4 v = (s < 0)
                 ? vinit
                 : inputs[((unsigned)(s * B_DIM + b)) * H4 + h4];
        out[((unsigned)(t * B_DIM + b)) * H4 + h4] = v;
    }
}

extern "C" void kernel_launch(void* const* d_in, const int* in_sizes, int n_in,
                              void* d_out, int out_size) {
    const float* inputs = (const float*)d_in[0];   // (T,B,H) f32
    const float* init_h = (const float*)d_in[1];   // (H,)    f32
    const int*   ops    = (const int*)d_in[2];     // (T,B)   i32
    float* out = (float*)d_out;                    // (T,B,H) f32

    fused_kernel<<<2 * B_DIM, 256>>>(
        (const float4*)inputs, (const float4*)init_h, ops, (float4*)out);
}

// round 6
// speedup vs baseline: 1.1214x; 1.0038x over previous
#include <cuda_runtime.h>
#include <cuda_bf16.h>

// Problem constants: T=64, B=512, H=512.
#define T_DIM 64
#define B_DIM 512
#define H_DIM 512
#define H4    (H_DIM / 4)            // 128 float4 per row
#define STRIDE (B_DIM * H4)          // float4 stride between consecutive t

// Grid: 2048 blocks x 128 threads. Block (b, quarter) covers lane b and 32 of
// the 128 float4 columns. Phase 1 (parallel, runs in 64 of 128 threads):
//   P[t] = prefix_sum(ops)[t]  (P[-1] = 0)
//   src[t] = -1                              if P[t] == 0
//          = max{ u <= t : P[u-1] == P[t]-1 } otherwise
__global__ void __launch_bounds__(128, 16) fused_kernel(
    const float4* __restrict__ inputs,   // (T,B,H) as float4
    const float4* __restrict__ init_h,   // (H,)    as float4
    const int*    __restrict__ ops,      // (T,B)
    float4*       __restrict__ out)      // (T,B,H) as float4
{
    __shared__ int s_P[T_DIM + 1];       // s_P[u] = P[u-1], s_P[0] = 0
    __shared__ int s_src[T_DIM];
    __shared__ int s_w0;

    const int bid = blockIdx.x;
    const int b   = bid >> 2;
    const int q   = bid & 3;
    const int tid = threadIdx.x;

    // ---- Phase 1a: two-warp inclusive scan of ops column b ----
    int p = 0;
    if (tid < T_DIM) {
        p = ops[tid * B_DIM + b];
        #pragma unroll
        for (int d = 1; d < 32; d <<= 1) {
            int n = __shfl_up_sync(0xFFFFFFFFu, p, d);
            if ((tid & 31) >= d) p += n;
        }
        if (tid == 31) s_w0 = p;
        if (tid == 0)  s_P[0] = 0;
    }
    __syncthreads();
    if (tid >= 32 && tid < T_DIM) p += s_w0;
    if (tid < T_DIM) s_P[tid + 1] = p;
    __syncthreads();

    // ---- Phase 1b: per-t backward search for the matching writer ----
    if (tid < T_DIM) {
        int Pt  = s_P[tid + 1];
        int src = -1;
        if (Pt > 0) {
            int target = Pt - 1;
            #pragma unroll 1
            for (int u = tid; u >= 0; --u) {
                if (s_P[u] == target) { src = u; break; }
            }
        }
        s_src[tid] = src;
    }
    __syncthreads();

    // ---- Phase 2: streaming gather-copy (64 t x 32 h4 per block) ----
    const int h4 = (q << 5) + (tid & 31);
    const int t0 = tid >> 5;                         // 0..3
    const float4* __restrict__ init_row = init_h + h4;
    const float4* __restrict__ in_base  = inputs + (unsigned)b * H4 + h4;
    float4*       __restrict__ out_base = out    + (unsigned)b * H4 + h4;

    #pragma unroll
    for (int i = 0; i < 16; i += 4) {
        // address select (no value-select, no per-iter LDS in the hot path)
        int s0 = s_src[t0 + (i + 0) * 4];
        int s1 = s_src[t0 + (i + 1) * 4];
        int s2 = s_src[t0 + (i + 2) * 4];
        int s3 = s_src[t0 + (i + 3) * 4];
        const float4* a0 = (s0 < 0) ? init_row : in_base + (unsigned)s0 * STRIDE;
        const float4* a1 = (s1 < 0) ? init_row : in_base + (unsigned)s1 * STRIDE;
        const float4* a2 = (s2 < 0) ? init_row : in_base + (unsigned)s2 * STRIDE;
        const float4* a3 = (s3 < 0) ? init_row : in_base + (unsigned)s3 * STRIDE;
        float4 v0 = __ldg(a0);
        float4 v1 = __ldg(a1);
        float4 v2 = __ldg(a2);
        float4 v3 = __ldg(a3);
        __stcs(out_base + (unsigned)(t0 + (i + 0) * 4) * STRIDE, v0);
        __stcs(out_base + (unsigned)(t0 + (i + 1) * 4) * STRIDE, v1);
        __stcs(out_base + (unsigned)(t0 + (i + 2) * 4) * STRIDE, v2);
        __stcs(out_base + (unsigned)(t0 + (i + 3) * 4) * STRIDE, v3);
    }
}

extern "C" void kernel_launch(void* const* d_in, const int* in_sizes, int n_in,
                              void* d_out, int out_size) {
    const float* inputs = (const float*)d_in[0];   // (T,B,H) f32
    const float* init_h = (const float*)d_in[1];   // (H,)    f32
    const int*   ops    = (const int*)d_in[2];     // (T,B)   i32
    float* out = (float*)d_out;                    // (T,B,H) f32

    fused_kernel<<<4 * B_DIM, 128>>>(
        (const float4*)inputs, (const float4*)init_h, ops, (float4*)out);
}